// round 1
// baseline (speedup 1.0000x reference)
#include <cuda_runtime.h>
#include <math.h>

#define TM 128
#define TN 64
#define TK 32
#define NTHREADS 256

// Fused 1x1-conv (GEMM) + YOLOv5 decode for one scale.
// P: [16, C, ny*nx]  W: [255, C]  Bias: [255]  anchors: [3,3,2]
// out: [16, 25200, 85]
__global__ __launch_bounds__(NTHREADS) void yolo_gemm_decode(
    const float* __restrict__ P,
    const float* __restrict__ W,
    const float* __restrict__ Bias,
    const float* __restrict__ anchors,
    float* __restrict__ out,
    int C, int ny, int nx, float stride_,
    int row_off, int scale_idx)
{
    const int nyx = ny * nx;
    __shared__ float As[TK][TM];
    __shared__ float Bs[TK][TN + 4];   // +4 pad: kills STS bank conflicts, keeps 16B row alignment

    const int tid = threadIdx.x;
    const int b   = blockIdx.z;
    const int m0  = blockIdx.x * TM;
    const int o0  = blockIdx.y * TN;

    const float* Pb = P + (size_t)b * C * nyx;

    float acc[8][4];
    #pragma unroll
    for (int r = 0; r < 8; r++)
        #pragma unroll
        for (int c = 0; c < 4; c++) acc[r][c] = 0.f;

    const int tx = tid & 15;   // 16 cols of threads -> 64 outputs
    const int ty = tid >> 4;   // 16 rows of threads -> 128 pixels

    const bool full_m = (m0 + TM) <= nyx;

    for (int k0 = 0; k0 < C; k0 += TK) {
        // ---- load A tile: TK x TM (pixels contiguous -> coalesced float4) ----
        if (full_m) {
            #pragma unroll
            for (int i = 0; i < 4; i++) {
                int idx4 = i * NTHREADS + tid;        // 0..1023 float4s
                int kt   = idx4 >> 5;                 // /32
                int mv   = (idx4 & 31) << 2;          // *4
                const float4 v = *reinterpret_cast<const float4*>(
                    Pb + (size_t)(k0 + kt) * nyx + m0 + mv);
                *reinterpret_cast<float4*>(&As[kt][mv]) = v;
            }
        } else {
            #pragma unroll
            for (int i = 0; i < 16; i++) {
                int idx = i * NTHREADS + tid;         // 0..4095
                int kt  = idx >> 7;
                int mv  = idx & 127;
                float v = 0.f;
                if (m0 + mv < nyx)
                    v = Pb[(size_t)(k0 + kt) * nyx + m0 + mv];
                As[kt][mv] = v;
            }
        }
        // ---- load B tile: 64 outputs x TK (W rows contiguous in c) ----
        #pragma unroll
        for (int i = 0; i < 2; i++) {
            int idx4 = i * NTHREADS + tid;            // 0..511 float4s
            int j    = idx4 >> 3;                     // output within tile
            int ktv  = (idx4 & 7) << 2;               // k within tile
            float4 v = make_float4(0.f, 0.f, 0.f, 0.f);
            if (o0 + j < 255)
                v = *reinterpret_cast<const float4*>(
                        W + (size_t)(o0 + j) * C + k0 + ktv);
            Bs[ktv + 0][j] = v.x;
            Bs[ktv + 1][j] = v.y;
            Bs[ktv + 2][j] = v.z;
            Bs[ktv + 3][j] = v.w;
        }
        __syncthreads();

        // ---- 8x4 register-tile FMA ----
        #pragma unroll
        for (int kt = 0; kt < TK; kt++) {
            float a[8], bw[4];
            *reinterpret_cast<float4*>(a)     = *reinterpret_cast<const float4*>(&As[kt][ty * 8]);
            *reinterpret_cast<float4*>(a + 4) = *reinterpret_cast<const float4*>(&As[kt][ty * 8 + 4]);
            *reinterpret_cast<float4*>(bw)    = *reinterpret_cast<const float4*>(&Bs[kt][tx * 4]);
            #pragma unroll
            for (int r = 0; r < 8; r++)
                #pragma unroll
                for (int c = 0; c < 4; c++)
                    acc[r][c] = fmaf(a[r], bw[c], acc[r][c]);
        }
        __syncthreads();
    }

    // ---- epilogue: bias + sigmoid + decode + scattered-but-mostly-coalesced store ----
    float aw[3], ah[3];
    #pragma unroll
    for (int a = 0; a < 3; a++) {
        aw[a] = anchors[scale_idx * 6 + a * 2 + 0];
        ah[a] = anchors[scale_idx * 6 + a * 2 + 1];
    }

    #pragma unroll
    for (int r = 0; r < 8; r++) {
        int m = m0 + ty * 8 + r;
        if (m >= nyx) continue;
        float gx = (float)(m % nx);
        float gy = (float)(m / nx);
        #pragma unroll
        for (int c = 0; c < 4; c++) {
            int o = o0 + tx * 4 + c;
            if (o >= 255) continue;
            int a = o / 85;
            int e = o - a * 85;
            float yv = acc[r][c] + Bias[o];
            float s  = 1.f / (1.f + expf(-yv));
            float v;
            if (e == 0)      v = (2.f * s + gx - 0.5f) * stride_;
            else if (e == 1) v = (2.f * s + gy - 0.5f) * stride_;
            else if (e == 2) { float t = 2.f * s; v = t * t * aw[a]; }
            else if (e == 3) { float t = 2.f * s; v = t * t * ah[a]; }
            else             v = s;
            size_t row = (size_t)b * 25200 + (size_t)row_off + (size_t)a * nyx + (size_t)m;
            out[row * 85 + e] = v;
        }
    }
}

extern "C" void kernel_launch(void* const* d_in, const int* in_sizes, int n_in,
                              void* d_out, int out_size) {
    const float* p0 = (const float*)d_in[0];
    const float* p1 = (const float*)d_in[1];
    const float* p2 = (const float*)d_in[2];
    const float* w0 = (const float*)d_in[3];
    const float* b0 = (const float*)d_in[4];
    const float* w1 = (const float*)d_in[5];
    const float* b1 = (const float*)d_in[6];
    const float* w2 = (const float*)d_in[7];
    const float* b2 = (const float*)d_in[8];
    const float* an = (const float*)d_in[9];
    float* out = (float*)d_out;

    dim3 block(NTHREADS);
    {   // scale 0: C=256, 80x80, stride 8
        dim3 grid((6400 + TM - 1) / TM, 4, 16);
        yolo_gemm_decode<<<grid, block>>>(p0, w0, b0, an, out, 256, 80, 80, 8.f, 0, 0);
    }
    {   // scale 1: C=512, 40x40, stride 16
        dim3 grid((1600 + TM - 1) / TM, 4, 16);
        yolo_gemm_decode<<<grid, block>>>(p1, w1, b1, an, out, 512, 40, 40, 16.f, 19200, 1);
    }
    {   // scale 2: C=1024, 20x20, stride 32
        dim3 grid((400 + TM - 1) / TM, 4, 16);
        yolo_gemm_decode<<<grid, block>>>(p2, w2, b2, an, out, 1024, 20, 20, 32.f, 24000, 2);
    }
}

// round 4
// speedup vs baseline: 1.3656x; 1.3656x over previous
#include <cuda_runtime.h>
#include <cstdint>
#include <math.h>

#define NTHR 256

__device__ __forceinline__ float to_tf32(float x) {
    asm("cvt.rna.tf32.f32 %0, %1;" : "=f"(x) : "f"(x));
    return x;
}

// smem float offsets
#define A_F(buf)  ((buf) * 9216)            // As: 256 rows x 36 floats, 2 buffers
#define B_F(buf)  (18432 + (buf) * 4352)    // Bs: 32 rows x 136 floats, 2 buffers
#define ST_F      0                          // stage: 255 x 129 floats (reuses GEMM bufs)
#define SBIAS_F   32896                      // 256 floats
#define SANC_F    33152                      // 6 floats
#define SMEM_BYTES (33160 * 4)

// ---- chunk loaders (prefetch to regs) ----
__device__ __forceinline__ void ldgA(float4 a[8], const float* __restrict__ W,
                                     int C, int k0, int tid) {
    #pragma unroll
    for (int i = 0; i < 8; i++) {
        int idx = i * NTHR + tid;
        int n = idx >> 3, q = idx & 7;
        if (n < 255) a[i] = *reinterpret_cast<const float4*>(W + (size_t)n * C + k0 + q * 4);
        else         a[i] = make_float4(0.f, 0.f, 0.f, 0.f);
    }
}
__device__ __forceinline__ void ldgB(float4 b[4], const float* __restrict__ Pb,
                                     int NYX, int m0, int k0, int tid) {
    #pragma unroll
    for (int i = 0; i < 4; i++) {
        int idx = i * NTHR + tid;
        int k = idx >> 5, col = (idx & 31) * 4;
        int m = m0 + col;
        if (m + 3 >= NYX) m = NYX - 4;        // clamp: values unused, just in-bounds
        b[i] = *reinterpret_cast<const float4*>(Pb + (size_t)(k0 + k) * NYX + m);
    }
}
__device__ __forceinline__ void stsA(float* As, const float4 a[8], int tid) {
    #pragma unroll
    for (int i = 0; i < 8; i++) {
        int idx = i * NTHR + tid;
        int n = idx >> 3, q = idx & 7;
        float4 v = a[i];
        v.x = to_tf32(v.x); v.y = to_tf32(v.y); v.z = to_tf32(v.z); v.w = to_tf32(v.w);
        *reinterpret_cast<float4*>(As + n * 36 + q * 4) = v;
    }
}
__device__ __forceinline__ void stsB(float* Bs, const float4 b[4], int tid) {
    #pragma unroll
    for (int i = 0; i < 4; i++) {
        int idx = i * NTHR + tid;
        int k = idx >> 5, col = (idx & 31) * 4;
        float4 v = b[i];
        v.x = to_tf32(v.x); v.y = to_tf32(v.y); v.z = to_tf32(v.z); v.w = to_tf32(v.w);
        *reinterpret_cast<float4*>(Bs + k * 136 + col) = v;
    }
}

template <int C, int NY, int NX, int ROW_OFF, int SCALE>
__global__ __launch_bounds__(NTHR, 1) void yolo_hmma(
    const float* __restrict__ P, const float* __restrict__ W,
    const float* __restrict__ Bias, const float* __restrict__ anchors,
    float* __restrict__ out)
{
    constexpr int NYX = NY * NX;
    constexpr float STRIDE = (float)(8 << SCALE);
    constexpr int NCHUNK = C / 32;
    extern __shared__ float smemf[];

    const int tid = threadIdx.x;
    const int wid = tid >> 5;
    const int lid = tid & 31;
    const int r4 = lid >> 2;       // groupID
    const int l4 = lid & 3;        // threadID_in_group
    const int o_w = (wid >> 1) * 64;   // warp output base (M)
    const int p_w = (wid & 1) * 64;    // warp pixel base (N)
    const int b = blockIdx.y;
    const int m0 = blockIdx.x * 128;
    const float* Pb = P + (size_t)b * C * NYX;

    // bias + anchors to smem (region beyond GEMM buffers)
    if (tid < 255) smemf[SBIAS_F + tid] = Bias[tid];
    if (tid == 255) smemf[SBIAS_F + 255] = 0.f;
    if (tid < 6) smemf[SANC_F + tid] = anchors[SCALE * 6 + tid];

    float acc[4][8][4];
    #pragma unroll
    for (int am = 0; am < 4; am++)
        #pragma unroll
        for (int an = 0; an < 8; an++)
            #pragma unroll
            for (int j = 0; j < 4; j++) acc[am][an][j] = 0.f;

    float4 apf[8], bpf[4];
    ldgA(apf, W, C, 0, tid);
    ldgB(bpf, Pb, NYX, m0, 0, tid);
    stsA(smemf + A_F(0), apf, tid);
    stsB(smemf + B_F(0), bpf, tid);
    __syncthreads();

    #pragma unroll 1
    for (int ci = 0; ci < NCHUNK; ci++) {
        const float* As = smemf + A_F(ci & 1);
        const float* Bs = smemf + B_F(ci & 1);
        const bool more = (ci + 1 < NCHUNK);
        if (more) {
            ldgA(apf, W, C, (ci + 1) * 32, tid);
            ldgB(bpf, Pb, NYX, m0, (ci + 1) * 32, tid);
        }
        #pragma unroll
        for (int ks = 0; ks < 4; ks++) {
            const int kk = ks * 8;
            uint32_t af[4][4], bf[8][2];
            #pragma unroll
            for (int am = 0; am < 4; am++) {
                const float* ba = As + (o_w + am * 16 + r4) * 36 + kk + l4;
                af[am][0] = __float_as_uint(ba[0]);
                af[am][1] = __float_as_uint(ba[8 * 36]);
                af[am][2] = __float_as_uint(ba[4]);
                af[am][3] = __float_as_uint(ba[8 * 36 + 4]);
            }
            #pragma unroll
            for (int an = 0; an < 8; an++) {
                const float* bb = Bs + (kk + l4) * 136 + p_w + an * 8 + r4;
                bf[an][0] = __float_as_uint(bb[0]);
                bf[an][1] = __float_as_uint(bb[4 * 136]);
            }
            #pragma unroll
            for (int am = 0; am < 4; am++)
                #pragma unroll
                for (int an = 0; an < 8; an++)
                    asm volatile(
                        "mma.sync.aligned.m16n8k8.row.col.f32.tf32.tf32.f32 "
                        "{%0,%1,%2,%3}, {%4,%5,%6,%7}, {%8,%9}, {%0,%1,%2,%3};\n"
                        : "+f"(acc[am][an][0]), "+f"(acc[am][an][1]),
                          "+f"(acc[am][an][2]), "+f"(acc[am][an][3])
                        : "r"(af[am][0]), "r"(af[am][1]), "r"(af[am][2]), "r"(af[am][3]),
                          "r"(bf[an][0]), "r"(bf[an][1]));
        }
        if (more) {
            stsA(smemf + A_F((ci + 1) & 1), apf, tid);
            stsB(smemf + B_F((ci + 1) & 1), bpf, tid);
        }
        __syncthreads();
    }

    // ---- epilogue: decode + stage (stage reuses GEMM buffer space) ----
    float* stage = smemf + ST_F;
    const float* sbias = smemf + SBIAS_F;
    const float* sanc = smemf + SANC_F;

    #pragma unroll
    for (int am = 0; am < 4; am++) {
        #pragma unroll
        for (int j = 0; j < 4; j++) {
            const int o = o_w + am * 16 + r4 + ((j >> 1) << 3);
            if (o >= 255) continue;
            const int a = (o * 772) >> 16;
            const int e = o - a * 85;
            const float bias = sbias[o];
            #pragma unroll
            for (int an = 0; an < 8; an++) {
                const int pix = p_w + an * 8 + 2 * l4 + (j & 1);
                const int m = m0 + pix;
                const float y = acc[am][an][j] + bias;
                const float s = 1.f / (1.f + __expf(-y));
                float v = s;
                if (e == 0) {
                    float gx = (float)(m % NX);
                    v = (2.f * s + gx - 0.5f) * STRIDE;
                } else if (e == 1) {
                    float gy = (float)(m / NX);
                    v = (2.f * s + gy - 0.5f) * STRIDE;
                } else if (e == 2) {
                    float t = 2.f * s; v = t * t * sanc[a * 2];
                } else if (e == 3) {
                    float t = 2.f * s; v = t * t * sanc[a * 2 + 1];
                }
                stage[o * 129 + pix] = v;
            }
        }
    }
    __syncthreads();

    // ---- coalesced copy-out: rows of 85 floats ----
    for (int rr = wid; rr < 3 * 128; rr += 8) {
        const int a = rr >> 7;
        const int mlr = rr & 127;
        const int mg = m0 + mlr;
        if (mg >= NYX) continue;
        float* orow = out + ((size_t)b * 25200 + ROW_OFF + (size_t)a * NYX + mg) * 85;
        const float* src = stage + a * 85 * 129 + mlr;
        for (int e = lid; e < 85; e += 32)
            orow[e] = src[e * 129];
    }
}

extern "C" void kernel_launch(void* const* d_in, const int* in_sizes, int n_in,
                              void* d_out, int out_size) {
    const float* p0 = (const float*)d_in[0];
    const float* p1 = (const float*)d_in[1];
    const float* p2 = (const float*)d_in[2];
    const float* w0 = (const float*)d_in[3];
    const float* b0 = (const float*)d_in[4];
    const float* w1 = (const float*)d_in[5];
    const float* b1 = (const float*)d_in[6];
    const float* w2 = (const float*)d_in[7];
    const float* b2 = (const float*)d_in[8];
    const float* an = (const float*)d_in[9];
    float* out = (float*)d_out;

    cudaFuncSetAttribute(yolo_hmma<256, 80, 80, 0, 0>,
                         cudaFuncAttributeMaxDynamicSharedMemorySize, SMEM_BYTES);
    cudaFuncSetAttribute(yolo_hmma<512, 40, 40, 19200, 1>,
                         cudaFuncAttributeMaxDynamicSharedMemorySize, SMEM_BYTES);
    cudaFuncSetAttribute(yolo_hmma<1024, 20, 20, 24000, 2>,
                         cudaFuncAttributeMaxDynamicSharedMemorySize, SMEM_BYTES);

    dim3 blk(NTHR);
    yolo_hmma<256, 80, 80, 0, 0><<<dim3(50, 16), blk, SMEM_BYTES>>>(p0, w0, b0, an, out);
    yolo_hmma<512, 40, 40, 19200, 1><<<dim3(13, 16), blk, SMEM_BYTES>>>(p1, w1, b1, an, out);
    yolo_hmma<1024, 20, 20, 24000, 2><<<dim3(4, 16), blk, SMEM_BYTES>>>(p2, w2, b2, an, out);
}

// round 9
// speedup vs baseline: 1.7877x; 1.3091x over previous
#include <cuda_runtime.h>
#include <cstdint>
#include <math.h>

#define NTHR 512

// pack two floats -> bf16x2 word (lo = first k, hi = second k)
__device__ __forceinline__ uint32_t pack_bf16(float lo, float hi) {
    uint32_t w;
    asm("cvt.rn.bf16x2.f32 %0, %1, %2;" : "=r"(w) : "f"(hi), "f"(lo));
    return w;
}

// smem word offsets
#define A_F(buf)  ((buf) * 4224)            // A: 16 kwords x 264 (256 n + pad), x2
#define B_F(buf)  (8448 + (buf) * 2176)     // B: 16 kpairs x 136 (128 m + pad), x2
#define ST_F      0                          // stage 255 x 129 floats (reuses GEMM bufs)
#define SBIAS_F   32896
#define SANC_F    33152
#define SMEM_BYTES (33160 * 4)

template <int C, int NY, int NX, int ROW_OFF, int SCALE>
__global__ __launch_bounds__(NTHR, 1) void yolo_bf16(
    const float* __restrict__ P, const float* __restrict__ W,
    const float* __restrict__ Bias, const float* __restrict__ anchors,
    float* __restrict__ out)
{
    constexpr int NYX = NY * NX;
    constexpr float STRIDE = (float)(8 << SCALE);
    constexpr int NCHUNK = C / 32;
    extern __shared__ float smemf[];
    uint32_t* smemw = reinterpret_cast<uint32_t*>(smemf);

    const int tid = threadIdx.x;
    const int wid = tid >> 5;
    const int lid = tid & 31;
    const int r4 = lid >> 2;           // groupID
    const int l4 = lid & 3;            // thread-in-group
    const int o_w = (wid >> 2) * 64;   // warp output base (M), 4 groups
    const int p_w = (wid & 3) * 32;    // warp pixel base (N), 4 groups
    const int b = blockIdx.y;
    const int m0 = blockIdx.x * 128;
    const float* Pb = P + (size_t)b * C * NYX;

    if (tid < 255) smemf[SBIAS_F + tid] = Bias[tid];
    if (tid == 255) smemf[SBIAS_F + 255] = 0.f;
    if (tid < 6) smemf[SANC_F + tid] = anchors[SCALE * 6 + tid];

    const int bj = wid;                // B kpair group = warp id (16 warps, 2 k-rows each)
    const int bm4 = lid * 4;           // B m offset

    float acc[4][4][4];
    #pragma unroll
    for (int am = 0; am < 4; am++)
        #pragma unroll
        for (int an = 0; an < 4; an++)
            #pragma unroll
            for (int j = 0; j < 4; j++) acc[am][an][j] = 0.f;

    float4 apf[4];
    float4 bpf[2];

    auto ldgA = [&](int k0) {
        #pragma unroll
        for (int i = 0; i < 4; i++) {
            int idx = i * NTHR + tid;
            int n = idx & 255, q = idx >> 8;
            if (n < 255)
                apf[i] = *reinterpret_cast<const float4*>(W + (size_t)n * C + k0 + q * 4);
            else
                apf[i] = make_float4(0.f, 0.f, 0.f, 0.f);
        }
    };
    auto ldgB = [&](int k0) {
        int m = m0 + bm4;
        if (m + 3 >= NYX) m = NYX - 4;
        bpf[0] = *reinterpret_cast<const float4*>(Pb + (size_t)(k0 + 2 * bj) * NYX + m);
        bpf[1] = *reinterpret_cast<const float4*>(Pb + (size_t)(k0 + 2 * bj + 1) * NYX + m);
    };
    auto stsAB = [&](int buf) {
        uint32_t* A = smemw + A_F(buf);
        #pragma unroll
        for (int i = 0; i < 4; i++) {
            int idx = i * NTHR + tid;
            int n = idx & 255, q = idx >> 8;
            A[(2 * q) * 264 + n]     = pack_bf16(apf[i].x, apf[i].y);
            A[(2 * q + 1) * 264 + n] = pack_bf16(apf[i].z, apf[i].w);
        }
        uint32_t* B = smemw + B_F(buf) + bj * 136 + bm4;
        uint4 w;
        w.x = pack_bf16(bpf[0].x, bpf[1].x);
        w.y = pack_bf16(bpf[0].y, bpf[1].y);
        w.z = pack_bf16(bpf[0].z, bpf[1].z);
        w.w = pack_bf16(bpf[0].w, bpf[1].w);
        *reinterpret_cast<uint4*>(B) = w;
    };

    ldgA(0); ldgB(0);
    stsAB(0);
    __syncthreads();

    #pragma unroll 1
    for (int ci = 0; ci < NCHUNK; ci++) {
        const uint32_t* As = smemw + A_F(ci & 1);
        const uint32_t* Bs = smemw + B_F(ci & 1);
        const bool more = (ci + 1 < NCHUNK);
        if (more) { ldgA((ci + 1) * 32); ldgB((ci + 1) * 32); }

        #pragma unroll
        for (int ks = 0; ks < 2; ks++) {
            const int kw = ks * 8 + l4;
            uint32_t af[4][4], bf[4][2];
            #pragma unroll
            for (int am = 0; am < 4; am++) {
                const uint32_t* ba = As + kw * 264 + o_w + am * 16 + r4;
                af[am][0] = ba[0];
                af[am][1] = ba[8];
                af[am][2] = ba[4 * 264];
                af[am][3] = ba[4 * 264 + 8];
            }
            #pragma unroll
            for (int an = 0; an < 4; an++) {
                const uint32_t* bb = Bs + kw * 136 + p_w + an * 8 + r4;
                bf[an][0] = bb[0];
                bf[an][1] = bb[4 * 136];
            }
            #pragma unroll
            for (int am = 0; am < 4; am++)
                #pragma unroll
                for (int an = 0; an < 4; an++)
                    asm volatile(
                        "mma.sync.aligned.m16n8k16.row.col.f32.bf16.bf16.f32 "
                        "{%0,%1,%2,%3}, {%4,%5,%6,%7}, {%8,%9}, {%0,%1,%2,%3};\n"
                        : "+f"(acc[am][an][0]), "+f"(acc[am][an][1]),
                          "+f"(acc[am][an][2]), "+f"(acc[am][an][3])
                        : "r"(af[am][0]), "r"(af[am][1]), "r"(af[am][2]), "r"(af[am][3]),
                          "r"(bf[an][0]), "r"(bf[an][1]));
        }
        __syncthreads();
        if (more) stsAB((ci + 1) & 1);
        __syncthreads();
    }

    // ---- epilogue: decode + transposed stage ----
    float* stage = smemf + ST_F;
    const float* sbias = smemf + SBIAS_F;
    const float* sanc = smemf + SANC_F;

    #pragma unroll
    for (int am = 0; am < 4; am++) {
        #pragma unroll
        for (int j = 0; j < 4; j++) {
            const int o = o_w + am * 16 + r4 + ((j >> 1) << 3);
            if (o >= 255) continue;
            const int a = (o * 772) >> 16;
            const int e = o - a * 85;
            const float bias = sbias[o];
            #pragma unroll
            for (int an = 0; an < 4; an++) {
                const int pix = p_w + an * 8 + 2 * l4 + (j & 1);
                const int m = m0 + pix;
                const float y = acc[am][an][j] + bias;
                const float s = 1.f / (1.f + __expf(-y));
                float v = s;
                if (e == 0) {
                    float gx = (float)(m % NX);
                    v = (2.f * s + gx - 0.5f) * STRIDE;
                } else if (e == 1) {
                    float gy = (float)(m / NX);
                    v = (2.f * s + gy - 0.5f) * STRIDE;
                } else if (e == 2) {
                    float t = 2.f * s; v = t * t * sanc[a * 2];
                } else if (e == 3) {
                    float t = 2.f * s; v = t * t * sanc[a * 2 + 1];
                }
                stage[o * 129 + pix] = v;
            }
        }
    }
    __syncthreads();

    // ---- coalesced copy-out: rows of 85 floats ----
    for (int rr = wid; rr < 3 * 128; rr += 16) {
        const int a = rr >> 7;
        const int mlr = rr & 127;
        const int mg = m0 + mlr;
        if (mg >= NYX) continue;
        float* orow = out + ((size_t)b * 25200 + ROW_OFF + (size_t)a * NYX + mg) * 85;
        const float* src = stage + a * 85 * 129 + mlr;
        #pragma unroll 3
        for (int e = lid; e < 85; e += 32)
            orow[e] = src[e * 129];
    }
}

extern "C" void kernel_launch(void* const* d_in, const int* in_sizes, int n_in,
                              void* d_out, int out_size) {
    const float* p0 = (const float*)d_in[0];
    const float* p1 = (const float*)d_in[1];
    const float* p2 = (const float*)d_in[2];
    const float* w0 = (const float*)d_in[3];
    const float* b0 = (const float*)d_in[4];
    const float* w1 = (const float*)d_in[5];
    const float* b1 = (const float*)d_in[6];
    const float* w2 = (const float*)d_in[7];
    const float* b2 = (const float*)d_in[8];
    const float* an = (const float*)d_in[9];
    float* out = (float*)d_out;

    cudaFuncSetAttribute(yolo_bf16<256, 80, 80, 0, 0>,
                         cudaFuncAttributeMaxDynamicSharedMemorySize, SMEM_BYTES);
    cudaFuncSetAttribute(yolo_bf16<512, 40, 40, 19200, 1>,
                         cudaFuncAttributeMaxDynamicSharedMemorySize, SMEM_BYTES);
    cudaFuncSetAttribute(yolo_bf16<1024, 20, 20, 24000, 2>,
                         cudaFuncAttributeMaxDynamicSharedMemorySize, SMEM_BYTES);

    dim3 blk(NTHR);
    yolo_bf16<256, 80, 80, 0, 0><<<dim3(50, 16), blk, SMEM_BYTES>>>(p0, w0, b0, an, out);
    yolo_bf16<512, 40, 40, 19200, 1><<<dim3(13, 16), blk, SMEM_BYTES>>>(p1, w1, b1, an, out);
    yolo_bf16<1024, 20, 20, 24000, 2><<<dim3(4, 16), blk, SMEM_BYTES>>>(p2, w2, b2, an, out);
}

// round 11
// speedup vs baseline: 2.6359x; 1.4745x over previous
#include <cuda_runtime.h>
#include <cstdint>
#include <math.h>

#define NTHR 256

__device__ __forceinline__ uint32_t pack_bf16(float lo, float hi) {
    uint32_t w;
    asm("cvt.rn.bf16x2.f32 %0, %1, %2;" : "=r"(w) : "f"(hi), "f"(lo));
    return w;
}

// smem word offsets (total 8456 words = 33.8KB)
#define A_F(buf)  ((buf) * 2176)           // A: 16 kwords x 136 (128 out + 8 pad)
#define B_F(buf)  (4352 + (buf) * 1152)    // B: 16 kpairs x 72 (64 pix + 8 pad)
#define ST_F      0                         // stage: 128 x 65 floats (overlaps A/B)
#define SBIAS_F   8320                      // 128 floats (this CTA's outputs)
#define SANC_F    8448                      // 6 floats
#define SMEM_W    8456

template <int C, int NY, int NX, int ROW_OFF, int SCALE>
__global__ __launch_bounds__(NTHR, 3) void yolo_bf16(
    const float* __restrict__ P, const float* __restrict__ W,
    const float* __restrict__ Bias, const float* __restrict__ anchors,
    float* __restrict__ out)
{
    constexpr int NYX = NY * NX;
    constexpr float STRIDE = (float)(8 << SCALE);
    constexpr int NCHUNK = C / 32;
    __shared__ float smemf[SMEM_W];
    uint32_t* smemw = reinterpret_cast<uint32_t*>(smemf);

    const int tid = threadIdx.x;
    const int wid = tid >> 5;
    const int lid = tid & 31;
    const int r4 = lid >> 2;           // groupID
    const int l4 = lid & 3;            // thread-in-group
    const int o_w = (wid >> 1) * 32;   // warp output base (4 M-groups)
    const int p_w = (wid & 1) * 32;    // warp pixel base  (2 N-groups)
    const int b  = blockIdx.y;
    const int oh = blockIdx.z;         // output half: 0 -> outs 0..127, 1 -> 128..254
    const int m0 = blockIdx.x * 64;
    const float* Pb = P + (size_t)b * C * NYX;

    if (tid < 128) {
        int g = oh * 128 + tid;
        smemf[SBIAS_F + tid] = (g < 255) ? Bias[g] : 0.f;
    }
    if (tid < 6) smemf[SANC_F + tid] = anchors[SCALE * 6 + tid];

    // B load coords: 16 kpairs x 16 threads covering 64 pixels
    const int bj  = tid >> 4;          // kpair 0..15
    const int bmq = (tid & 15) * 4;    // pixel offset

    float acc[2][4][4];
    #pragma unroll
    for (int am = 0; am < 2; am++)
        #pragma unroll
        for (int an = 0; an < 4; an++)
            #pragma unroll
            for (int j = 0; j < 4; j++) acc[am][an][j] = 0.f;

    float4 apf[4], bpf[2];

    auto ldgA = [&](int k0) {
        #pragma unroll
        for (int i = 0; i < 4; i++) {
            int idx = i * NTHR + tid;          // 0..1023
            int nl = idx >> 3, q = idx & 7;    // nl: 0..127, q: 0..7
            int n = oh * 128 + nl;
            if (n < 255)
                apf[i] = *reinterpret_cast<const float4*>(W + (size_t)n * C + k0 + q * 4);
            else
                apf[i] = make_float4(0.f, 0.f, 0.f, 0.f);
        }
    };
    auto ldgB = [&](int k0) {
        int m = m0 + bmq;
        if (m + 3 >= NYX) m = NYX - 4;
        bpf[0] = *reinterpret_cast<const float4*>(Pb + (size_t)(k0 + 2 * bj) * NYX + m);
        bpf[1] = *reinterpret_cast<const float4*>(Pb + (size_t)(k0 + 2 * bj + 1) * NYX + m);
    };
    auto stsAB = [&](int buf) {
        uint32_t* A = smemw + A_F(buf);
        #pragma unroll
        for (int i = 0; i < 4; i++) {
            int idx = i * NTHR + tid;
            int nl = idx >> 3, q = idx & 7;
            A[(2 * q) * 136 + nl]     = pack_bf16(apf[i].x, apf[i].y);
            A[(2 * q + 1) * 136 + nl] = pack_bf16(apf[i].z, apf[i].w);
        }
        uint32_t* B = smemw + B_F(buf) + bj * 72 + bmq;
        uint4 w;
        w.x = pack_bf16(bpf[0].x, bpf[1].x);
        w.y = pack_bf16(bpf[0].y, bpf[1].y);
        w.z = pack_bf16(bpf[0].z, bpf[1].z);
        w.w = pack_bf16(bpf[0].w, bpf[1].w);
        *reinterpret_cast<uint4*>(B) = w;
    };

    ldgA(0); ldgB(0);
    stsAB(0);
    __syncthreads();

    #pragma unroll 1
    for (int ci = 0; ci < NCHUNK; ci++) {
        const uint32_t* As = smemw + A_F(ci & 1);
        const uint32_t* Bs = smemw + B_F(ci & 1);
        const bool more = (ci + 1 < NCHUNK);
        if (more) { ldgA((ci + 1) * 32); ldgB((ci + 1) * 32); }

        #pragma unroll
        for (int ks = 0; ks < 2; ks++) {
            const int kw = ks * 8 + l4;
            uint32_t af[2][4], bf[4][2];
            #pragma unroll
            for (int am = 0; am < 2; am++) {
                const uint32_t* ba = As + kw * 136 + o_w + am * 16 + r4;
                af[am][0] = ba[0];
                af[am][1] = ba[8];
                af[am][2] = ba[4 * 136];
                af[am][3] = ba[4 * 136 + 8];
            }
            #pragma unroll
            for (int an = 0; an < 4; an++) {
                const uint32_t* bb = Bs + kw * 72 + p_w + an * 8 + r4;
                bf[an][0] = bb[0];
                bf[an][1] = bb[4 * 72];
            }
            #pragma unroll
            for (int am = 0; am < 2; am++)
                #pragma unroll
                for (int an = 0; an < 4; an++)
                    asm volatile(
                        "mma.sync.aligned.m16n8k16.row.col.f32.bf16.bf16.f32 "
                        "{%0,%1,%2,%3}, {%4,%5,%6,%7}, {%8,%9}, {%0,%1,%2,%3};\n"
                        : "+f"(acc[am][an][0]), "+f"(acc[am][an][1]),
                          "+f"(acc[am][an][2]), "+f"(acc[am][an][3])
                        : "r"(af[am][0]), "r"(af[am][1]), "r"(af[am][2]), "r"(af[am][3]),
                          "r"(bf[an][0]), "r"(bf[an][1]));
        }
        if (more) stsAB((ci + 1) & 1);
        __syncthreads();   // single barrier per chunk (double-buffered)
    }

    // ---- epilogue: decode + transposed stage (stage overlaps GEMM bufs) ----
    float* stage = smemf + ST_F;
    const float* sbias = smemf + SBIAS_F;
    const float* sanc  = smemf + SANC_F;

    #pragma unroll
    for (int am = 0; am < 2; am++) {
        #pragma unroll
        for (int j = 0; j < 4; j++) {
            const int ol = o_w + am * 16 + r4 + ((j >> 1) << 3);   // 0..127 local
            const int o  = oh * 128 + ol;
            if (o >= 255) continue;
            const int a = (o * 772) >> 16;
            const int e = o - a * 85;
            const float bias = sbias[ol];
            #pragma unroll
            for (int an = 0; an < 4; an++) {
                const int pix = p_w + an * 8 + 2 * l4 + (j & 1);   // 0..63
                const int m = m0 + pix;
                const float y = acc[am][an][j] + bias;
                const float s = 1.f / (1.f + __expf(-y));
                float v = s;
                if (e == 0) {
                    float gx = (float)(m % NX);
                    v = (2.f * s + gx - 0.5f) * STRIDE;
                } else if (e == 1) {
                    float gy = (float)(m / NX);
                    v = (2.f * s + gy - 0.5f) * STRIDE;
                } else if (e == 2) {
                    float t = 2.f * s; v = t * t * sanc[a * 2];
                } else if (e == 3) {
                    float t = 2.f * s; v = t * t * sanc[a * 2 + 1];
                }
                stage[ol * 65 + pix] = v;
            }
        }
    }
    __syncthreads();

    // ---- coalesced copy-out: this CTA owns 2 (anchor, e-range) slabs ----
    // oh=0: (a=0, e 0..85), (a=1, e 0..43);  oh=1: (a=1, e 43..85), (a=2, e 0..85)
    for (int rr = wid; rr < 128; rr += 8) {
        const int r   = rr >> 6;         // range 0/1
        const int mlr = rr & 63;
        const int mg  = m0 + mlr;
        if (mg >= NYX) continue;
        const int a  = oh + r;
        const int e0 = (r == 0 && oh == 1) ? 43 : 0;
        const int e1 = (r == 1 && oh == 0) ? 43 : 85;
        float* orow = out + ((size_t)b * 25200 + ROW_OFF + (size_t)a * NYX + mg) * 85;
        const float* src = stage + mlr;  // stage[(85a+e-128oh)*65 + mlr]
        const int lo_base = 85 * a - 128 * oh;
        for (int e = e0 + lid; e < e1; e += 32)
            orow[e] = src[(lo_base + e) * 65];
    }
}

extern "C" void kernel_launch(void* const* d_in, const int* in_sizes, int n_in,
                              void* d_out, int out_size) {
    const float* p0 = (const float*)d_in[0];
    const float* p1 = (const float*)d_in[1];
    const float* p2 = (const float*)d_in[2];
    const float* w0 = (const float*)d_in[3];
    const float* b0 = (const float*)d_in[4];
    const float* w1 = (const float*)d_in[5];
    const float* b1 = (const float*)d_in[6];
    const float* w2 = (const float*)d_in[7];
    const float* b2 = (const float*)d_in[8];
    const float* an = (const float*)d_in[9];
    float* out = (float*)d_out;

    dim3 blk(NTHR);
    yolo_bf16<256, 80, 80, 0, 0><<<dim3(100, 16, 2), blk>>>(p0, w0, b0, an, out);
    yolo_bf16<512, 40, 40, 19200, 1><<<dim3(25, 16, 2), blk>>>(p1, w1, b1, an, out);
    yolo_bf16<1024, 20, 20, 24000, 2><<<dim3(7, 16, 2), blk>>>(p2, w2, b2, an, out);
}

// round 13
// speedup vs baseline: 2.8961x; 1.0987x over previous
#include <cuda_runtime.h>
#include <cstdint>
#include <math.h>

#define NTHR 256

__device__ __forceinline__ uint32_t pack_bf16(float lo, float hi) {
    uint32_t w;
    asm("cvt.rn.bf16x2.f32 %0, %1, %2;" : "=r"(w) : "f"(hi), "f"(lo));
    return w;
}

// smem word offsets (total 8456 words = 33.8KB)
#define A_F(buf)  ((buf) * 2176)           // A: 16 kwords x 136 (128 out + 8 pad)
#define B_F(buf)  (4352 + (buf) * 1152)    // B: 16 kpairs x 72 (64 pix + 8 pad)
#define ST_F      0                         // stage: 128 x 65 floats (overlaps A/B)
#define SBIAS_F   8320                      // 128 floats (this CTA's outputs)
#define SANC_F    8448                      // 6 floats
#define SMEM_W    8456

template <int C, int NY, int NX, int ROW_OFF, int SCALE>
__global__ __launch_bounds__(NTHR, 3) void yolo_bf16(
    const float* __restrict__ P, const float* __restrict__ W,
    const float* __restrict__ Bias, const float* __restrict__ anchors,
    float* __restrict__ out)
{
    constexpr int NYX = NY * NX;
    constexpr float STRIDE = (float)(8 << SCALE);
    constexpr int NCHUNK = C / 32;
    __shared__ float smemf[SMEM_W];
    uint32_t* smemw = reinterpret_cast<uint32_t*>(smemf);

    const int tid = threadIdx.x;
    const int wid = tid >> 5;
    const int lid = tid & 31;
    const int r4 = lid >> 2;           // groupID
    const int l4 = lid & 3;            // thread-in-group
    const int o_w = (wid >> 1) * 32;   // warp output base (4 M-groups)
    const int p_w = (wid & 1) * 32;    // warp pixel base  (2 N-groups)
    const int b  = blockIdx.y;
    const int oh = blockIdx.z;         // output half: 0 -> outs 0..127, 1 -> 128..254
    const int m0 = blockIdx.x * 64;
    const float* Pb = P + (size_t)b * C * NYX;

    if (tid < 128) {
        int g = oh * 128 + tid;
        smemf[SBIAS_F + tid] = (g < 255) ? Bias[g] : 0.f;
    }
    if (tid < 6) smemf[SANC_F + tid] = anchors[SCALE * 6 + tid];

    // B load coords: 16 kpairs x 16 threads covering 64 pixels
    const int bj  = tid >> 4;          // kpair 0..15
    const int bmq = (tid & 15) * 4;    // pixel offset

    float acc[2][4][4];
    #pragma unroll
    for (int am = 0; am < 2; am++)
        #pragma unroll
        for (int an = 0; an < 4; an++)
            #pragma unroll
            for (int j = 0; j < 4; j++) acc[am][an][j] = 0.f;

    float4 apf[4], bpf[2];

    auto ldgA = [&](int k0) {
        #pragma unroll
        for (int i = 0; i < 4; i++) {
            int idx = i * NTHR + tid;          // 0..1023
            int nl = idx >> 3, q = idx & 7;    // nl: 0..127, q: 0..7
            int n = oh * 128 + nl;
            if (n < 255)
                apf[i] = *reinterpret_cast<const float4*>(W + (size_t)n * C + k0 + q * 4);
            else
                apf[i] = make_float4(0.f, 0.f, 0.f, 0.f);
        }
    };
    auto ldgB = [&](int k0) {
        int m = m0 + bmq;
        if (m + 3 >= NYX) m = NYX - 4;
        bpf[0] = *reinterpret_cast<const float4*>(Pb + (size_t)(k0 + 2 * bj) * NYX + m);
        bpf[1] = *reinterpret_cast<const float4*>(Pb + (size_t)(k0 + 2 * bj + 1) * NYX + m);
    };
    auto stsAB = [&](int buf) {
        uint32_t* A = smemw + A_F(buf);
        #pragma unroll
        for (int i = 0; i < 4; i++) {
            int idx = i * NTHR + tid;
            int nl = idx >> 3, q = idx & 7;
            A[(2 * q) * 136 + nl]     = pack_bf16(apf[i].x, apf[i].y);
            A[(2 * q + 1) * 136 + nl] = pack_bf16(apf[i].z, apf[i].w);
        }
        uint32_t* B = smemw + B_F(buf) + bj * 72 + bmq;
        uint4 w;
        w.x = pack_bf16(bpf[0].x, bpf[1].x);
        w.y = pack_bf16(bpf[0].y, bpf[1].y);
        w.z = pack_bf16(bpf[0].z, bpf[1].z);
        w.w = pack_bf16(bpf[0].w, bpf[1].w);
        *reinterpret_cast<uint4*>(B) = w;
    };

    ldgA(0); ldgB(0);
    stsAB(0);
    __syncthreads();

    #pragma unroll 1
    for (int ci = 0; ci < NCHUNK; ci++) {
        const uint32_t* As = smemw + A_F(ci & 1);
        const uint32_t* Bs = smemw + B_F(ci & 1);
        const bool more = (ci + 1 < NCHUNK);
        if (more) { ldgA((ci + 1) * 32); ldgB((ci + 1) * 32); }

        #pragma unroll
        for (int ks = 0; ks < 2; ks++) {
            const int kw = ks * 8 + l4;
            uint32_t af[2][4], bf[4][2];
            #pragma unroll
            for (int am = 0; am < 2; am++) {
                const uint32_t* ba = As + kw * 136 + o_w + am * 16 + r4;
                af[am][0] = ba[0];
                af[am][1] = ba[8];
                af[am][2] = ba[4 * 136];
                af[am][3] = ba[4 * 136 + 8];
            }
            #pragma unroll
            for (int an = 0; an < 4; an++) {
                const uint32_t* bb = Bs + kw * 72 + p_w + an * 8 + r4;
                bf[an][0] = bb[0];
                bf[an][1] = bb[4 * 72];
            }
            #pragma unroll
            for (int am = 0; am < 2; am++)
                #pragma unroll
                for (int an = 0; an < 4; an++)
                    asm volatile(
                        "mma.sync.aligned.m16n8k16.row.col.f32.bf16.bf16.f32 "
                        "{%0,%1,%2,%3}, {%4,%5,%6,%7}, {%8,%9}, {%0,%1,%2,%3};\n"
                        : "+f"(acc[am][an][0]), "+f"(acc[am][an][1]),
                          "+f"(acc[am][an][2]), "+f"(acc[am][an][3])
                        : "r"(af[am][0]), "r"(af[am][1]), "r"(af[am][2]), "r"(af[am][3]),
                          "r"(bf[an][0]), "r"(bf[an][1]));
        }
        if (more) stsAB((ci + 1) & 1);
        __syncthreads();   // single barrier per chunk (double-buffered)
    }

    // ---- epilogue: decode via unified polynomial v = (s*c2 + c1)*s + c0 ----
    float* stage = smemf + ST_F;
    const float* sbias = smemf + SBIAS_F;
    const float* sanc  = smemf + SANC_F;

    // pre-scaled grid tables for this thread's 8 pixel slots: [an][parity]
    float gxs[4][2], gys[4][2];
    #pragma unroll
    for (int an = 0; an < 4; an++)
        #pragma unroll
        for (int par = 0; par < 2; par++) {
            int m = m0 + p_w + an * 8 + 2 * l4 + par;
            gxs[an][par] = (float)(m % NX) * STRIDE - 0.5f * STRIDE;
            gys[an][par] = (float)(m / NX) * STRIDE - 0.5f * STRIDE;
        }

    #pragma unroll
    for (int am = 0; am < 2; am++) {
        #pragma unroll
        for (int j = 0; j < 4; j++) {
            const int ol = o_w + am * 16 + r4 + ((j >> 1) << 3);   // 0..127 local
            const int o  = oh * 128 + ol;
            if (o >= 255) continue;
            const int a = (o * 772) >> 16;
            const int e = o - a * 85;
            const float bias = sbias[ol];
            // per-(am,j) constants (per-lane, hoisted out of pixel loop)
            float c1 = 1.f, c2 = 0.f, selx = 0.f, sely = 0.f;
            if (e == 0)      { c1 = 2.f * STRIDE; selx = 1.f; }
            else if (e == 1) { c1 = 2.f * STRIDE; sely = 1.f; }
            else if (e == 2) { c1 = 0.f; c2 = 4.f * sanc[a * 2]; }
            else if (e == 3) { c1 = 0.f; c2 = 4.f * sanc[a * 2 + 1]; }
            const int par = j & 1;
            float* strow = stage + ol * 65 + p_w + 2 * l4 + par;
            #pragma unroll
            for (int an = 0; an < 4; an++) {
                const float y = acc[am][an][j] + bias;
                const float s = 1.f / (1.f + __expf(-y));
                const float c0 = selx * gxs[an][par] + sely * gys[an][par];
                strow[an * 8] = fmaf(fmaf(s, c2, c1), s, c0);
            }
        }
    }
    __syncthreads();

    // ---- coalesced copy-out: this CTA owns 2 (anchor, e-range) slabs ----
    // oh=0: (a=0, e 0..85), (a=1, e 0..43);  oh=1: (a=1, e 43..85), (a=2, e 0..85)
    for (int rr = wid; rr < 128; rr += 8) {
        const int r   = rr >> 6;         // range 0/1
        const int mlr = rr & 63;
        const int mg  = m0 + mlr;
        if (mg >= NYX) continue;
        const int a  = oh + r;
        const int e0 = (r == 0 && oh == 1) ? 43 : 0;
        const int e1 = (r == 1 && oh == 0) ? 43 : 85;
        float* orow = out + ((size_t)b * 25200 + ROW_OFF + (size_t)a * NYX + mg) * 85;
        const float* src = stage + mlr;  // stage[(85a+e-128oh)*65 + mlr]
        const int lo_base = 85 * a - 128 * oh;
        for (int e = e0 + lid; e < e1; e += 32)
            orow[e] = src[(lo_base + e) * 65];
    }
}

extern "C" void kernel_launch(void* const* d_in, const int* in_sizes, int n_in,
                              void* d_out, int out_size) {
    const float* p0 = (const float*)d_in[0];
    const float* p1 = (const float*)d_in[1];
    const float* p2 = (const float*)d_in[2];
    const float* w0 = (const float*)d_in[3];
    const float* b0 = (const float*)d_in[4];
    const float* w1 = (const float*)d_in[5];
    const float* b1 = (const float*)d_in[6];
    const float* w2 = (const float*)d_in[7];
    const float* b2 = (const float*)d_in[8];
    const float* an = (const float*)d_in[9];
    float* out = (float*)d_out;

    dim3 blk(NTHR);
    yolo_bf16<256, 80, 80, 0, 0><<<dim3(100, 16, 2), blk>>>(p0, w0, b0, an, out);
    yolo_bf16<512, 40, 40, 19200, 1><<<dim3(25, 16, 2), blk>>>(p1, w1, b1, an, out);
    yolo_bf16<1024, 20, 20, 24000, 2><<<dim3(7, 16, 2), blk>>>(p2, w2, b2, an, out);
}